// round 2
// baseline (speedup 1.0000x reference)
#include <cuda_runtime.h>
#include <math.h>

// BPR loss with negatives:
//   per_sample[b] = -( sum_{i<L, j<L, k<S} log_sigmoid( out[b,i,lab[b,j]] - out[b,i,neg[b,j,k]] ) ) / (L^2 * S)
//   result = sum_b per_sample[b]          (shape [1], float32)
//
// Inputs (metadata order) — NOTE: harness converts int64 -> int32:
//   d_in[0] output  : float32 [B, T, V]
//   d_in[1] labels  : int32   [B, T]
//   d_in[2] x_lens  : int32   [B]
//   d_in[3] uids    : int32   [B, 1]   (unused)
//   d_in[4] neg_ids : int32   [B, T, S]

__global__ void zero_out_kernel(float* __restrict__ out) {
    if (threadIdx.x == 0) out[0] = 0.0f;
}

__device__ __forceinline__ float warp_reduce_add(float v) {
#pragma unroll
    for (int off = 16; off > 0; off >>= 1)
        v += __shfl_down_sync(0xFFFFFFFFu, v, off);
    return v;
}

__global__ void __launch_bounds__(256)
bpr_loss_kernel(const float* __restrict__ out3d,   // [B,T,V]
                const int* __restrict__ labels,    // [B,T]
                const int* __restrict__ x_lens,    // [B]
                const int* __restrict__ neg_ids,   // [B,T,S]
                float* __restrict__ result,        // [1]
                int T, int V, int S)
{
    const int b = blockIdx.y;
    const int i = blockIdx.x;
    const int L = x_lens[b];
    if (i >= L) return;

    const float* __restrict__ row = out3d + ((size_t)b * T + i) * (size_t)V;
    const int* __restrict__ lab = labels + (size_t)b * T;
    const int* __restrict__ neg = neg_ids + (size_t)b * T * S;

    float acc = 0.0f;
    for (int j = threadIdx.x; j < L; j += blockDim.x) {
        const int c_pos = lab[j];
        const float pv = __ldg(row + c_pos);
        for (int k = 0; k < S; ++k) {
            const int c_neg = neg[j * S + k];
            const float nv = __ldg(row + c_neg);
            const float d = pv - nv;
            // stable log_sigmoid: min(d,0) - log1p(exp(-|d|))
            acc += fminf(d, 0.0f) - log1pf(__expf(-fabsf(d)));
        }
    }

    // block reduction
    __shared__ float warp_sums[8];
    const int lane = threadIdx.x & 31;
    const int wid  = threadIdx.x >> 5;
    acc = warp_reduce_add(acc);
    if (lane == 0) warp_sums[wid] = acc;
    __syncthreads();
    if (wid == 0) {
        float v = (lane < (blockDim.x >> 5)) ? warp_sums[lane] : 0.0f;
        v = warp_reduce_add(v);
        if (lane == 0) {
            const float Lf = (float)L;
            const float scale = -1.0f / (Lf * Lf * (float)S);
            atomicAdd(result, v * scale);
        }
    }
}

extern "C" void kernel_launch(void* const* d_in, const int* in_sizes, int n_in,
                              void* d_out, int out_size)
{
    const float* out3d   = (const float*)d_in[0];
    const int*   labels  = (const int*)d_in[1];
    const int*   x_lens  = (const int*)d_in[2];
    const int*   neg_ids = (const int*)d_in[4];
    float* result = (float*)d_out;

    const int B = in_sizes[2];                 // x_lens has B elements
    const int T = in_sizes[1] / B;             // labels: B*T
    const int V = in_sizes[0] / (B * T);       // output: B*T*V
    const int S = in_sizes[4] / (B * T);       // neg_ids: B*T*S

    zero_out_kernel<<<1, 32>>>(result);

    dim3 grid(T, B);
    bpr_loss_kernel<<<grid, 256>>>(out3d, labels, x_lens, neg_ids, result, T, V, S);
}

// round 3
// speedup vs baseline: 1.0144x; 1.0144x over previous
#include <cuda_runtime.h>
#include <math.h>

// BPR loss:
//   per_sample[b] = -( sum_{i<L, j<L, k<S} log_sigmoid( out[b,i,lab[b,j]] - out[b,i,neg[b,j,k]] ) ) / (L^2 * S)
//   result = sum_b per_sample[b]     (shape [1], float32)
//
// Inputs (metadata order; harness delivers int64 as int32):
//   d_in[0] output  : float32 [B, T, V]
//   d_in[1] labels  : int32   [B, T]
//   d_in[2] x_lens  : int32   [B]
//   d_in[3] uids    : int32   [B, 1]   (unused)
//   d_in[4] neg_ids : int32   [B, T, S]

#define ROWS_PER_BLOCK 4
#define SUBW 64          // lanes per row-group

__global__ void zero_out_kernel(float* __restrict__ out) {
    if (threadIdx.x == 0) out[0] = 0.0f;
}

__device__ __forceinline__ float warp_reduce_add(float v) {
#pragma unroll
    for (int off = 16; off > 0; off >>= 1)
        v += __shfl_down_sync(0xFFFFFFFFu, v, off);
    return v;
}

__device__ __forceinline__ float log_sigmoid_fast(float d) {
    // min(d,0) - log(1 + exp(-|d|)); exp arg in [-inf,0] -> e in (0,1], log arg in (1,2]
    return fminf(d, 0.0f) - __logf(1.0f + __expf(-fabsf(d)));
}

__global__ void __launch_bounds__(256)
bpr_loss_kernel(const float* __restrict__ out3d,   // [B,T,V]
                const int* __restrict__ labels,    // [B,T]
                const int* __restrict__ x_lens,    // [B]
                const int* __restrict__ neg_ids,   // [B,T,S]
                float* __restrict__ result,        // [1]
                int T, int V, int S)
{
    const int b = blockIdx.y;
    const int L = x_lens[b];
    const int i0 = blockIdx.x * ROWS_PER_BLOCK;
    if (i0 >= L) return;

    const int sub = threadIdx.x & (SUBW - 1);   // j-lane within row-group
    const int ri  = threadIdx.x / SUBW;         // row index within block
    const int i   = i0 + ri;

    const int* __restrict__ lab = labels + (size_t)b * T;
    const int* __restrict__ neg = neg_ids + (size_t)b * T * S;

    float acc = 0.0f;
    if (i < L) {
        const float* __restrict__ row = out3d + ((size_t)b * T + i) * (size_t)V;
        if (S == 1) {
            // batched: collect up to 4 index pairs, issue 8 gathers together, then compute
            for (int base = 0; base < L; base += SUBW * 4) {
                int cp[4], cn[4];
                float pv[4], nv[4];
#pragma unroll
                for (int m = 0; m < 4; ++m) {
                    const int j = base + m * SUBW + sub;
                    const bool v = j < L;
                    cp[m] = v ? __ldg(lab + j) : -1;
                    cn[m] = v ? __ldg(neg + j) : 0;
                }
#pragma unroll
                for (int m = 0; m < 4; ++m) {
                    if (cp[m] >= 0) {
                        pv[m] = __ldg(row + cp[m]);
                        nv[m] = __ldg(row + cn[m]);
                    }
                }
#pragma unroll
                for (int m = 0; m < 4; ++m) {
                    if (cp[m] >= 0) acc += log_sigmoid_fast(pv[m] - nv[m]);
                }
            }
        } else {
            // general S fallback
            for (int j = sub; j < L; j += SUBW) {
                const int c_pos = __ldg(lab + j);
                const float pvv = __ldg(row + c_pos);
                for (int k = 0; k < S; ++k) {
                    const int c_neg = __ldg(neg + (size_t)j * S + k);
                    acc += log_sigmoid_fast(pvv - __ldg(row + c_neg));
                }
            }
        }
    }

    // block reduction (all 256 threads participate; invalid rows contribute 0)
    __shared__ float warp_sums[8];
    const int lane = threadIdx.x & 31;
    const int wid  = threadIdx.x >> 5;
    acc = warp_reduce_add(acc);
    if (lane == 0) warp_sums[wid] = acc;
    __syncthreads();
    if (wid == 0) {
        float v = (lane < 8) ? warp_sums[lane] : 0.0f;
        v = warp_reduce_add(v);
        if (lane == 0) {
            const float Lf = (float)L;
            atomicAdd(result, v * (-1.0f / (Lf * Lf * (float)S)));
        }
    }
}

extern "C" void kernel_launch(void* const* d_in, const int* in_sizes, int n_in,
                              void* d_out, int out_size)
{
    const float* out3d   = (const float*)d_in[0];
    const int*   labels  = (const int*)d_in[1];
    const int*   x_lens  = (const int*)d_in[2];
    const int*   neg_ids = (const int*)d_in[4];
    float* result = (float*)d_out;

    const int B = in_sizes[2];                 // x_lens: B
    const int T = in_sizes[1] / B;             // labels: B*T
    const int V = in_sizes[0] / (B * T);       // output: B*T*V
    const int S = in_sizes[4] / (B * T);       // neg_ids: B*T*S

    zero_out_kernel<<<1, 32>>>(result);

    dim3 grid((T + ROWS_PER_BLOCK - 1) / ROWS_PER_BLOCK, B);
    bpr_loss_kernel<<<grid, 256>>>(out3d, labels, x_lens, neg_ids, result, T, V, S);
}